// round 13
// baseline (speedup 1.0000x reference)
#include <cuda_runtime.h>
#include <cuda_bf16.h>

// Idx2PixelLayer — R12: compact-then-gather two-pass.
//  K0 clear:     reset 2 counters.
//  K1 partition: split point ids into two DENSE lists by table half
//                (i0 < 1024 vs >= 1024) using block-aggregated compaction
//                (ballot/popc + 1 atomicAdd per half per block).
//  K2 gather x2: dense list, 2 points/thread unconditionally, table half
//                (67MB) pinned in L2 via evict_last; coords re-read (L2-hot),
//                out streamed with __stcs.

static constexpr int   HW    = 2048;
static constexpr int   CH    = 8;
static constexpr float MODV  = 2044.0f;   // H - 4
static constexpr int   SPLIT = 1024;
static constexpr int   CAP   = 1 << 20;   // max points for static lists (1e6 fits)

__device__ int g_cnt[2];
__device__ int g_list0[CAP];
__device__ int g_list1[CAP];

struct F8 { float v[8]; };

__device__ __forceinline__ F8 ldg_keep32(const float* p) {
    F8 r;
    asm volatile("ld.global.nc.L2::evict_last.v8.b32 {%0,%1,%2,%3,%4,%5,%6,%7}, [%8];"
                 : "=f"(r.v[0]), "=f"(r.v[1]), "=f"(r.v[2]), "=f"(r.v[3]),
                   "=f"(r.v[4]), "=f"(r.v[5]), "=f"(r.v[6]), "=f"(r.v[7])
                 : "l"(p));
    return r;
}

// floor-mod (python semantics) then +1 ; c in [1,2045) < 2048, so the
// reference's zero-mask (c0 > 2048) can never fire.
__device__ __forceinline__ void coord_prep(float cx, float cy,
                                           int& i0, int& i1,
                                           float& d0, float& d1)
{
    float c0 = fmodf(cx - 1.0f, MODV); if (c0 < 0.0f) c0 += MODV; c0 += 1.0f;
    float c1 = fmodf(cy - 1.0f, MODV); if (c1 < 0.0f) c1 += MODV; c1 += 1.0f;
    float f0 = floorf(c0), f1 = floorf(c1);
    d0 = c0 - f0; d1 = c1 - f1;
    i0 = (int)f0; i1 = (int)f1;
}

__global__ void k_clear()
{
    if (threadIdx.x < 2) g_cnt[threadIdx.x] = 0;
}

__global__ __launch_bounds__(256)
void k_partition(const float* __restrict__ coords, int n)
{
    int t = blockIdx.x * 256 + threadIdx.x;
    bool valid = (t < n);

    bool hi = false;
    if (valid) {
        // normal load (not streaming): keep coords resident in L2 for the
        // gather kernels' re-reads.
        float2 co = __ldg(reinterpret_cast<const float2*>(coords) + t);
        int i0, i1; float d0, d1;
        coord_prep(co.x, co.y, i0, i1, d0, d1);
        hi = (i0 >= SPLIT);
    }

    __shared__ int wcnt0[8], wcnt1[8], soff0[8], soff1[8];
    __shared__ int sbase0, sbase1;
    int wid = threadIdx.x >> 5, lane = threadIdx.x & 31;

    unsigned m0 = __ballot_sync(0xffffffffu, valid && !hi);
    unsigned m1 = __ballot_sync(0xffffffffu, valid &&  hi);
    if (lane == 0) { wcnt0[wid] = __popc(m0); wcnt1[wid] = __popc(m1); }
    __syncthreads();
    if (threadIdx.x == 0) {
        int s0 = 0, s1 = 0;
        #pragma unroll
        for (int w = 0; w < 8; w++) {
            soff0[w] = s0; s0 += wcnt0[w];
            soff1[w] = s1; s1 += wcnt1[w];
        }
        sbase0 = atomicAdd(&g_cnt[0], s0);
        sbase1 = atomicAdd(&g_cnt[1], s1);
    }
    __syncthreads();

    unsigned ltmask = (1u << lane) - 1u;
    if (valid) {
        if (!hi) g_list0[sbase0 + soff0[wid] + __popc(m0 & ltmask)] = t;
        else     g_list1[sbase1 + soff1[wid] + __popc(m1 & ltmask)] = t;
    }
}

__device__ __forceinline__ void gather_point(const float* __restrict__ visible,
                                             float2 co,
                                             F8& tl, F8& bl, F8& tr, F8& br,
                                             float& d0, float& d1)
{
    int i0, i1;
    coord_prep(co.x, co.y, i0, i1, d0, d1);
    const float* rowA = visible + ((size_t)i0 * HW + i1) * CH;  // [tl|bl] 64B
    const float* rowB = rowA + (size_t)HW * CH;                 // [tr|br] 64B
    tl = ldg_keep32(rowA);
    bl = ldg_keep32(rowA + 8);
    tr = ldg_keep32(rowB);
    br = ldg_keep32(rowB + 8);
}

__device__ __forceinline__ void bilerp_store(const F8& tl, const F8& bl,
                                             const F8& tr, const F8& br,
                                             float d0, float d1, float* outp)
{
    float o[8];
    #pragma unroll
    for (int k = 0; k < 8; k++) {
        float mt = tr.v[k] + d0 * (tl.v[k] - tr.v[k]);
        float mb = br.v[k] + d0 * (bl.v[k] - br.v[k]);
        o[k] = mb + d1 * (mt - mb);
    }
    float4* dst = reinterpret_cast<float4*>(outp);
    __stcs(dst + 0, make_float4(o[0], o[1], o[2], o[3]));
    __stcs(dst + 1, make_float4(o[4], o[5], o[6], o[7]));
}

__global__ __launch_bounds__(256)
void k_gather(const float* __restrict__ coords,
              const float* __restrict__ visible,
              float* __restrict__ out,
              const int* __restrict__ list,
              const int* __restrict__ cntp)
{
    int count = *cntp;
    int t = blockIdx.x * 256 + threadIdx.x;
    int jA = 2 * t;
    if (jA >= count) return;
    int jB = min(jA + 1, count - 1);        // clamp: no conditional loads

    int idA = __ldg(list + jA);
    int idB = __ldg(list + jB);
    float2 cA = __ldg(reinterpret_cast<const float2*>(coords) + idA);
    float2 cB = __ldg(reinterpret_cast<const float2*>(coords) + idB);

    F8 tlA, blA, trA, brA, tlB, blB, trB, brB;
    float d0A, d1A, d0B, d1B;
    gather_point(visible, cA, tlA, blA, trA, brA, d0A, d1A);
    gather_point(visible, cB, tlB, blB, trB, brB, d0B, d1B);

    bilerp_store(tlA, blA, trA, brA, d0A, d1A, out + (size_t)idA * CH);
    if (jA + 1 < count)
        bilerp_store(tlB, blB, trB, brB, d0B, d1B, out + (size_t)idB * CH);
}

// Fallback single-pass kernel (only used if n > CAP; never for this problem).
__global__ __launch_bounds__(256)
void k_simple(const float* __restrict__ coords,
              const float* __restrict__ visible,
              float* __restrict__ out, int n)
{
    int t = blockIdx.x * 256 + threadIdx.x;
    if (t >= n) return;
    float2 co = __ldg(reinterpret_cast<const float2*>(coords) + t);
    F8 tl, bl, tr, br; float d0, d1;
    gather_point(visible, co, tl, bl, tr, br, d0, d1);
    bilerp_store(tl, bl, tr, br, d0, d1, out + (size_t)t * CH);
}

extern "C" void kernel_launch(void* const* d_in, const int* in_sizes, int n_in,
                              void* d_out, int out_size)
{
    const float* coords  = (const float*)d_in[0];   // (N, 2) float32
    const float* visible = (const float*)d_in[1];   // (2048, 2048, 8) float32
    float* out = (float*)d_out;                     // (N, 8) float32

    int n = in_sizes[0] / 2;

    if (n > CAP) {   // safety fallback
        k_simple<<<(n + 255) / 256, 256>>>(coords, visible, out, n);
        return;
    }

    int blocks = (n + 255) / 256;
    int pairsMax = (n + 1) / 2;
    int gblocks = (pairsMax + 255) / 256;

    int* cnt0; int* cnt1;
    // device-symbol addresses are compile-time resolvable in device code, but
    // host needs them via pointer arithmetic on the symbol: use a tiny trick —
    // pass g_cnt as kernel argument via cudaGetSymbolAddress is not allowed
    // (no alloc, but GetSymbolAddress is fine and not an allocation).
    cudaGetSymbolAddress((void**)&cnt0, g_cnt);
    cnt1 = cnt0 + 1;
    int* list0; int* list1;
    cudaGetSymbolAddress((void**)&list0, g_list0);
    cudaGetSymbolAddress((void**)&list1, g_list1);

    k_clear<<<1, 32>>>();
    k_partition<<<blocks, 256>>>(coords, n);
    k_gather<<<gblocks, 256>>>(coords, visible, out, list0, cnt0);
    k_gather<<<gblocks, 256>>>(coords, visible, out, list1, cnt1);
}

// round 14
// speedup vs baseline: 1.7713x; 1.7713x over previous
#include <cuda_runtime.h>
#include <cuda_bf16.h>

// Idx2PixelLayer — FINAL (revert to measured-best R0 design, 39.0us).
// Bilinear gather from visible[2048,2048,8] at 1e6 random coords.
//
// Evidence from R2-R12: traffic is near-compulsory (~198MB vs 168MB floor);
// ~60% DRAM utilization is the random-access row-activation wall. Cache
// policy hints (R2), higher per-thread MLP (R4), temporal row-half passes
// (R6/R8), per-row binning (R3) and dense compaction (R12) all measured
// neutral-to-worse. Simple one-point-per-thread with 8 pre-issued float4
// gathers is the empirical optimum.
//
// Reference semantics:
//   c = floormod(coords - 1, 2044) + 1  (in [1,2045) -> zero-mask never fires,
//                                        implemented anyway via w0/w1 gating)
//   i = floor(c); d = c - i
//   mid_top    = top_right    + d0*(top_left    - top_right)
//   mid_bottom = bottom_right + d0*(bottom_left - bottom_right)
//   out = mid_bottom + d1*(mid_top - mid_bottom)

static constexpr int   HW   = 2048;
static constexpr int   CH   = 8;
static constexpr float MODV = 2044.0f;   // H - 4
static constexpr float DIMF = 2048.0f;

__global__ __launch_bounds__(256)
void idx2pixel_kernel(const float* __restrict__ coords,
                      const float* __restrict__ visible,
                      float* __restrict__ out,
                      int n)
{
    int t = blockIdx.x * blockDim.x + threadIdx.x;
    if (t >= n) return;

    float2 co = reinterpret_cast<const float2*>(coords)[t];

    // floor-mod (python semantics) then +1
    float c0 = fmodf(co.x - 1.0f, MODV); if (c0 < 0.0f) c0 += MODV; c0 += 1.0f;
    float c1 = fmodf(co.y - 1.0f, MODV); if (c1 < 0.0f) c1 += MODV; c1 += 1.0f;

    float f0 = floorf(c0), f1 = floorf(c1);
    float d0 = c0 - f0,   d1 = c1 - f1;
    int i0 = (int)f0, i1 = (int)f1;

    // visible[r][col] starts at (r*2048 + col)*8 floats; pixel = 2 float4s.
    // cols i1 and i1+1 are contiguous -> 4 consecutive float4 per row.
    const float4* rowA = reinterpret_cast<const float4*>(
        visible + ((size_t)i0 * HW + i1) * CH);
    const float4* rowB = rowA + (size_t)HW * CH / 4;   // +1 row = +4096 float4

    // Issue all 8 gathers before any compute (max MLP).
    float4 tl0 = rowA[0], tl1 = rowA[1];   // top_left     (i0,   i1)
    float4 bl0 = rowA[2], bl1 = rowA[3];   // bottom_left  (i0,   i1+1)
    float4 tr0 = rowB[0], tr1 = rowB[1];   // top_right    (i0+1, i1)
    float4 br0 = rowB[2], br1 = rowB[3];   // bottom_right (i0+1, i1+1)

    bool zero = (c0 > DIMF);   // reference checks only dim 0 (never true)
    float w0 = zero ? 0.0f : d0;
    float w1 = zero ? 0.0f : d1;

    float o[8];
    {
        const float* tl = &tl0.x; const float* tr = &tr0.x;
        const float* bl = &bl0.x; const float* br = &br0.x;
        #pragma unroll
        for (int k = 0; k < 4; k++) {
            float mt = tr[k] + w0 * (tl[k] - tr[k]);
            float mb = br[k] + w0 * (bl[k] - br[k]);
            o[k] = mb + w1 * (mt - mb);
        }
        tl = &tl1.x; tr = &tr1.x; bl = &bl1.x; br = &br1.x;
        #pragma unroll
        for (int k = 0; k < 4; k++) {
            float mt = tr[k] + w0 * (tl[k] - tr[k]);
            float mb = br[k] + w0 * (bl[k] - br[k]);
            o[4 + k] = mb + w1 * (mt - mb);
        }
    }
    if (zero) {
        #pragma unroll
        for (int k = 0; k < 8; k++) o[k] = 0.0f;
    }

    float4* dst = reinterpret_cast<float4*>(out + (size_t)t * CH);
    dst[0] = make_float4(o[0], o[1], o[2], o[3]);
    dst[1] = make_float4(o[4], o[5], o[6], o[7]);
}

extern "C" void kernel_launch(void* const* d_in, const int* in_sizes, int n_in,
                              void* d_out, int out_size)
{
    const float* coords  = (const float*)d_in[0];   // (N, 2) float32
    const float* visible = (const float*)d_in[1];   // (2048, 2048, 8) float32
    float* out = (float*)d_out;                     // (N, 8) float32

    int n = in_sizes[0] / 2;
    int threads = 256;
    int blocks = (n + threads - 1) / threads;
    idx2pixel_kernel<<<blocks, threads>>>(coords, visible, out, n);
}